// round 17
// baseline (speedup 1.0000x reference)
#include <cuda_runtime.h>
#include <cuda_fp16.h>
#include <mma.h>
#include <math.h>

using namespace nvcuda;
typedef unsigned int u32;

constexpr int TPB = 256;
constexpr int CH = 128, IMG_H = 256, IMG_W = 256, WSZ = 8;

// smem byte offsets, total 113664 (target: 2 CTAs/SM)
constexpr int WB0 = 0;        // weight slab buf0 (5120) 64x(32+8pad) fp16
constexpr int WB1 = 5120;     // weight slab buf1 (5120)
constexpr int XI  = 10240;    // X image [64][136] fp16: XT -> XS -> AO
constexpr int QI  = 27648;    // Q image [64][136]
constexpr int KI  = 45056;    // K image
constexpr int VI  = 62464;    // V image
constexpr int F0  = 79872;    // fp32 scratch: proj out [64][132] / S [64][68] / O [64][36] / final
constexpr int PP  = 97280;    // P fp16 [64][72] (upper part of F0 region)
constexpr int SMEM_BYTES = 113664;

// prepped weights: plain row-major [m][d][c] fp16 (hi only — pure fp16 GEMMs)
__device__ __align__(16) half WH16[4 * 16384];

__device__ __forceinline__ u32 smem_u32(const void* p) {
    u32 a;
    asm("{ .reg .u64 t; cvta.to.shared.u64 t, %1; cvt.u32.u64 %0, t; }"
        : "=r"(a) : "l"(p));
    return a;
}

__global__ void __launch_bounds__(256) prep_kernel(
    const float* __restrict__ Wq, const float* __restrict__ Wk,
    const float* __restrict__ Wv, const float* __restrict__ Wo)
{
    int m = blockIdx.y;
    const float* Ws = (m == 0) ? Wq : (m == 1) ? Wk : (m == 2) ? Wv : Wo;
    int idx = blockIdx.x * 256 + threadIdx.x;
    WH16[m * 16384 + idx] = __float2half_rn(Ws[idx]);
}

typedef wmma::fragment<wmma::matrix_a, 16, 16, 16, half, wmma::row_major> FA;
typedef wmma::fragment<wmma::matrix_b, 16, 16, 16, half, wmma::col_major> FBc;
typedef wmma::fragment<wmma::matrix_b, 16, 16, 16, half, wmma::row_major> FBr;
typedef wmma::fragment<wmma::accumulator, 16, 16, 16, float> FC;

// async copy of weight slab for global stage g: proj g>>3, kslab (g>>1)&3, dhalf g&1
// slab = 64 d-rows x 32 cols, dest stride 40 halves (80 B)
__device__ __forceinline__ void cp_slab(u32 sb, int bufoff, int g, int tid) {
    int proj = g >> 3, s = (g >> 1) & 3, hf = g & 1;
    int d = tid >> 2, sg = tid & 3;
    u32 dst = sb + bufoff + d * 80 + sg * 16;
    const char* src = (const char*)WH16 + proj * 32768 + (hf * 64 + d) * 256 + s * 64 + sg * 16;
    asm volatile("cp.async.cg.shared.global [%0], [%1], 16;" :: "r"(dst), "l"(src));
    asm volatile("cp.async.commit_group;" ::: "memory");
}
__device__ __forceinline__ void cp_wait0() {
    asm volatile("cp.async.wait_group 0;" ::: "memory");
}

// 8 stages of one projection: C[64 t][128 d] = X(Bimg) @ W^T -> F0 [t][132] fp32
__device__ __forceinline__ void proj8(char* smem, u32 sb, int g0,
                                      const half* Bimg, float* F0f,
                                      int mt, int wg, int tid)
{
    FC acc[2][2];
#pragma unroll
    for (int h2 = 0; h2 < 2; h2++)
#pragma unroll
        for (int j = 0; j < 2; j++) wmma::fill_fragment(acc[h2][j], 0.0f);

    for (int g = g0; g < g0 + 8; ++g) {
        if (g + 1 < 32) cp_slab(sb, ((g + 1) & 1) ? WB1 : WB0, g + 1, tid);
        const half* slab = (const half*)(smem + ((g & 1) ? WB1 : WB0));
        int s = (g >> 1) & 3, hf = g & 1;
#pragma unroll
        for (int kt = 0; kt < 2; kt++) {
            FA a;
            wmma::load_matrix_sync(a, Bimg + (mt * 16) * 136 + s * 32 + kt * 16, 136);
#pragma unroll
            for (int j = 0; j < 2; j++) {
                FBc bw;
                wmma::load_matrix_sync(bw, slab + (wg * 32 + j * 16) * 40 + kt * 16, 40);
                wmma::mma_sync(acc[hf][j], a, bw, acc[hf][j]);
            }
        }
        if (g == g0 + 7) {
#pragma unroll
            for (int h2 = 0; h2 < 2; h2++)
#pragma unroll
                for (int j = 0; j < 2; j++)
                    wmma::store_matrix_sync(F0f + (mt * 16) * 132 + h2 * 64 + wg * 32 + j * 16,
                                            acc[h2][j], 132, wmma::mem_row_major);
        }
        cp_wait0();
        __syncthreads();
    }
}

__global__ void __launch_bounds__(TPB, 2)
evsr_kernel(const float* __restrict__ tf, const float* __restrict__ sf,
            const float* __restrict__ lnw, const float* __restrict__ lnb,
            float* __restrict__ out)
{
    extern __shared__ char smem[];
    const int tid = threadIdx.x;
    const int w = tid >> 5;
    const int blk = blockIdx.x;
    const int b = blk >> 10, wy = (blk >> 5) & 31, wx = blk & 31;
    const int base = ((b * CH) << 16) + ((wy * WSZ) << 8) + (wx * WSZ);
    const u32 sb = smem_u32(smem);

    half* XIi = (half*)(smem + XI);
    half* Qi  = (half*)(smem + QI);
    half* Ki  = (half*)(smem + KI);
    half* Vi  = (half*)(smem + VI);
    float* F0f = (float*)(smem + F0);

    const int mt = w & 3, wg = w >> 2;    // proj tiling: t-tile, d-quad
    const float scl = 0.17677669529663687f;

    // ---- phase 0: start slab 0; build XT image ----
    cp_slab(sb, WB0, 0, tid);
#pragma unroll
    for (int k = 0; k < 32; k++) {
        int idx = tid + k * TPB;
        int c = idx >> 6, t = idx & 63;
        XIi[t * 136 + c] = __float2half_rn(tf[base + (c << 16) + ((t >> 3) << 8) + (t & 7)]);
    }
    cp_wait0();
    __syncthreads();

    // ---- Q projection (stages 0..7) + RoPE epilogue; load XS ----
    proj8(smem, sb, 0, XIi, F0f, mt, wg, tid);
#pragma unroll
    for (int k = 0; k < 16; k++) {
        int idx = tid + k * TPB;
        int i16 = idx & 15, h4 = (idx >> 4) & 3, t = idx >> 6;
        float freq = exp2f(-(float)i16 * 0.830482023721841f);
        float ang = (float)((t >> 3) + (t & 7)) * freq;
        float sv, cv; __sincosf(ang, &sv, &cv);
        int d1 = h4 * 32 + i16, d2 = d1 + 16;
        float q1 = F0f[t * 132 + d1], q2 = F0f[t * 132 + d2];
        Qi[t * 136 + d1] = __float2half_rn((q1 * cv - q2 * sv) * scl);
        Qi[t * 136 + d2] = __float2half_rn((q1 * sv + q2 * cv) * scl);
    }
#pragma unroll
    for (int k = 0; k < 32; k++) {
        int idx = tid + k * TPB;
        int c = idx >> 6, t = idx & 63;
        XIi[t * 136 + c] = __float2half_rn(sf[base + (c << 16) + ((t >> 3) << 8) + (t & 7)]);
    }
    __syncthreads();

    // ---- K projection (stages 8..15) + RoPE epilogue ----
    proj8(smem, sb, 8, XIi, F0f, mt, wg, tid);
#pragma unroll
    for (int k = 0; k < 16; k++) {
        int idx = tid + k * TPB;
        int i16 = idx & 15, h4 = (idx >> 4) & 3, t = idx >> 6;
        float freq = exp2f(-(float)i16 * 0.830482023721841f);
        float ang = (float)((t >> 3) + (t & 7)) * freq;
        float sv, cv; __sincosf(ang, &sv, &cv);
        int d1 = h4 * 32 + i16, d2 = d1 + 16;
        float k1 = F0f[t * 132 + d1], k2 = F0f[t * 132 + d2];
        Ki[t * 136 + d1] = __float2half_rn(k1 * cv - k2 * sv);
        Ki[t * 136 + d2] = __float2half_rn(k1 * sv + k2 * cv);
    }
    __syncthreads();

    // ---- V projection (stages 16..23) + convert epilogue ----
    proj8(smem, sb, 16, XIi, F0f, mt, wg, tid);
#pragma unroll
    for (int k = 0; k < 32; k++) {
        int idx = tid + k * TPB;
        int c = idx & 127, t = idx >> 7;
        Vi[t * 136 + c] = __float2half_rn(F0f[t * 132 + c]);
    }
    __syncthreads();

    // ---- attention: 4 per-head passes ----
    half* Pp = (half*)(smem + PP);
    const int mt2 = w >> 1, np = w & 1;

    for (int head = 0; head < 4; head++) {
        const int c0 = head * 32;
        {   // S = Q K^T : warp = (t-tile mt2, col-pair np), S fp32 in F0 stride 68
            FC s2[2];
            wmma::fill_fragment(s2[0], 0.0f);
            wmma::fill_fragment(s2[1], 0.0f);
#pragma unroll
            for (int kt = 0; kt < 2; kt++) {
                FA qa;
                wmma::load_matrix_sync(qa, Qi + (mt2 * 16) * 136 + c0 + kt * 16, 136);
#pragma unroll
                for (int j = 0; j < 2; j++) {
                    FBc kb;
                    wmma::load_matrix_sync(kb, Ki + ((np * 2 + j) * 16) * 136 + c0 + kt * 16, 136);
                    wmma::mma_sync(s2[j], qa, kb, s2[j]);
                }
            }
#pragma unroll
            for (int j = 0; j < 2; j++)
                wmma::store_matrix_sync(F0f + (mt2 * 16) * 68 + (np * 2 + j) * 16,
                                        s2[j], 68, wmma::mem_row_major);
        }
        __syncthreads();

        {   // softmax: 4 threads per row
            int rid = tid >> 2, q4 = tid & 3;
            float* Srow = F0f + rid * 68 + q4 * 16;
            float mx = -1e30f;
#pragma unroll
            for (int j = 0; j < 16; j++) mx = fmaxf(mx, Srow[j]);
            mx = fmaxf(mx, __shfl_xor_sync(0xffffffffu, mx, 1, 4));
            mx = fmaxf(mx, __shfl_xor_sync(0xffffffffu, mx, 2, 4));
            float e[16], s = 0.0f;
#pragma unroll
            for (int j = 0; j < 16; j++) { e[j] = __expf(Srow[j] - mx); s += e[j]; }
            s += __shfl_xor_sync(0xffffffffu, s, 1, 4);
            s += __shfl_xor_sync(0xffffffffu, s, 2, 4);
            float inv = 1.0f / s;
            half* Pd = Pp + rid * 72 + q4 * 16;
#pragma unroll
            for (int j = 0; j < 16; j++) Pd[j] = __float2half_rn(e[j] * inv);
        }
        __syncthreads();

        {   // O = P V : warp = (t-tile mt2, 16-col nd); O fp32 in F0 stride 36
            FC o;
            wmma::fill_fragment(o, 0.0f);
            int nd = np;
#pragma unroll
            for (int kt = 0; kt < 4; kt++) {
                FA pa;
                wmma::load_matrix_sync(pa, Pp + (mt2 * 16) * 72 + kt * 16, 72);
                FBr vb;
                wmma::load_matrix_sync(vb, Vi + (kt * 16) * 136 + c0 + nd * 16, 136);
                wmma::mma_sync(o, pa, vb, o);
            }
            wmma::store_matrix_sync(F0f + (mt2 * 16) * 36 + nd * 16, o, 36,
                                    wmma::mem_row_major);
        }
        __syncthreads();

        // AO columns for this head -> X image (fp16)
#pragma unroll
        for (int k = 0; k < 8; k++) {
            int idx = tid + k * TPB;
            int c = idx & 31, t = idx >> 5;
            XIi[t * 136 + c0 + c] = __float2half_rn(F0f[t * 36 + c]);
        }
        __syncthreads();
    }

    // ---- Wo projection (stages 24..31), B = AO image ----
    proj8(smem, sb, 24, XIi, F0f, mt, wg, tid);

    // ---- LayerNorm + residual (residual & ln params from global) ----
    {
        int t = tid >> 2, q4 = tid & 3;
        float s1 = 0.0f, s2 = 0.0f;
#pragma unroll
        for (int i = 0; i < 32; i++) {
            float v = F0f[t * 132 + q4 * 32 + i];
            s1 += v; s2 += v * v;
        }
        s1 += __shfl_xor_sync(0xffffffffu, s1, 1, 4);
        s1 += __shfl_xor_sync(0xffffffffu, s1, 2, 4);
        s2 += __shfl_xor_sync(0xffffffffu, s2, 1, 4);
        s2 += __shfl_xor_sync(0xffffffffu, s2, 2, 4);
        float mu = s1 * (1.0f / 128.0f);
        float var = s2 * (1.0f / 128.0f) - mu * mu;
        float inv = rsqrtf(var + 1e-5f);
        int trow = (t >> 3) << 8, tcol = t & 7;
#pragma unroll
        for (int i = 0; i < 32; i++) {
            int c = q4 * 32 + i;
            float r = tf[base + (c << 16) + trow + tcol];
            float v = F0f[t * 132 + c];
            F0f[t * 132 + c] = (v - mu) * inv * __ldg(lnw + c) + __ldg(lnb + c) + r;
        }
    }
    __syncthreads();

    // ---- store ----
#pragma unroll
    for (int k = 0; k < 32; k++) {
        int idx = tid + k * TPB;
        int c = idx >> 6, t = idx & 63;
        out[base + (c << 16) + ((t >> 3) << 8) + (t & 7)] = F0f[t * 132 + c];
    }
}

extern "C" void kernel_launch(void* const* d_in, const int* in_sizes, int n_in,
                              void* d_out, int out_size)
{
    const float* tf  = (const float*)d_in[0];
    const float* sf  = (const float*)d_in[1];
    const float* Wq  = (const float*)d_in[2];
    const float* Wk  = (const float*)d_in[3];
    const float* Wv  = (const float*)d_in[4];
    const float* Wo  = (const float*)d_in[5];
    const float* lnw = (const float*)d_in[6];
    const float* lnb = (const float*)d_in[7];
    float* out = (float*)d_out;

    int B = in_sizes[0] / (CH * IMG_H * IMG_W);
    if (B < 1) B = 1;
    int n_windows = B * (IMG_H / WSZ) * (IMG_W / WSZ);

    dim3 pg(64, 4);
    prep_kernel<<<pg, 256>>>(Wq, Wk, Wv, Wo);

    cudaFuncSetAttribute(evsr_kernel, cudaFuncAttributeMaxDynamicSharedMemorySize,
                         SMEM_BYTES);
    evsr_kernel<<<n_windows, TPB, SMEM_BYTES>>>(tf, sf, lnw, lnb, out);
}